// round 1
// baseline (speedup 1.0000x reference)
#include <cuda_runtime.h>
#include <math.h>

// ---------------- problem constants ----------------
#define Bb   64
#define Hh   15
#define Tt   16      // H + 1 (cls)
#define Ff   32      // F_CONT + F_CAT
#define Dd   512
#define NHh  8
#define HDd  64
#define Ll   4
#define DFFf 2048
#define NTOK (Bb*Tt*Ff)          // 32768 rows
#define EPSc 1e-7f

// ---------------- scratch (device globals; no allocation allowed) ----------------
__device__ float g_seq [NTOK*Dd];        // 64 MB  activations
__device__ float g_ln  [NTOK*Dd];        // 64 MB  LN out / attn out
__device__ float g_qkv [NTOK*3*Dd];      // 192 MB qkv (also reused as pool-tanh buf)
__device__ float g_ffn [NTOK*DFFf];      // 256 MB ffn hidden
__device__ float g_s   [NTOK];           // pool scores
__device__ float g_pool[Bb*Tt*Dd];       // pooled per (b,t)
__device__ float g_comb[Bb*Hh*2*Dd];     // concat(horse, race_ctx)
__device__ float g_feat[Bb*Hh*Dd];       // projected features
__device__ float g_u   [Bb*Hh*Dd];       // energy pre-activation (p-independent part)

// ---------------- helpers ----------------
__device__ __forceinline__ float warp_sum(float v){
#pragma unroll
    for (int o = 16; o > 0; o >>= 1) v += __shfl_xor_sync(0xffffffffu, v, o);
    return v;
}

__device__ __forceinline__ float gelu_f(float x){
    float x3 = x*x*x;
    float t  = tanhf(0.7978845608028654f*(x + 0.044715f*x3));
    return 0.5f*x*(1.f + t);
}
__device__ __forceinline__ float gelu_grad(float x){
    float x2 = x*x;
    float t  = tanhf(0.7978845608028654f*(x + 0.044715f*x2*x));
    float sech2 = 1.f - t*t;
    return 0.5f*(1.f + t) + 0.5f*x*sech2*0.7978845608028654f*(1.f + 3.f*0.044715f*x2);
}

// ---------------- embedding ----------------
__global__ __launch_bounds__(256)
void embed_kernel(const float* __restrict__ x_cont, const int* __restrict__ x_cat,
                  const float* __restrict__ emb_w, const float* __restrict__ emb_b,
                  const float* __restrict__ cat_emb, const float* __restrict__ cls,
                  float* __restrict__ seq)
{
    int idx = blockIdx.x*256 + threadIdx.x;          // < NTOK*Dd (exact grid)
    int d = idx & 511;
    int f = (idx >> 9)  & 31;
    int t = (idx >> 14) & 15;
    int b =  idx >> 18;
    float v;
    if (t == Tt-1) {
        v = cls[f*Dd + d];
    } else if (f < 24) {
        v = x_cont[(b*Hh + t)*24 + f]*emb_w[f*Dd + d] + emb_b[f*Dd + d];
    } else {
        int fc = f - 24;
        int c  = x_cat[(b*Hh + t)*8 + fc];
        v = cat_emb[((size_t)fc*50 + c)*Dd + d];
    }
    seq[idx] = v;
}

// ---------------- layernorm (one 128-thread block per row, D=512) ----------------
__global__ __launch_bounds__(128)
void ln_kernel(const float* __restrict__ X, float* __restrict__ Y,
               const float* __restrict__ gg, const float* __restrict__ bb)
{
    int row = blockIdx.x;
    int tid = threadIdx.x;
    const float4* xr = (const float4*)(X + (size_t)row*Dd);
    float4 v = xr[tid];
    __shared__ float red[4];
    float s = v.x + v.y + v.z + v.w;
    s = warp_sum(s);
    if ((tid & 31) == 0) red[tid >> 5] = s;
    __syncthreads();
    float mean = (red[0]+red[1]+red[2]+red[3]) * (1.f/Dd);
    float d0 = v.x-mean, d1 = v.y-mean, d2 = v.z-mean, d3 = v.w-mean;
    float q = d0*d0 + d1*d1 + d2*d2 + d3*d3;
    __syncthreads();
    q = warp_sum(q);
    if ((tid & 31) == 0) red[tid >> 5] = q;
    __syncthreads();
    float var = (red[0]+red[1]+red[2]+red[3]) * (1.f/Dd);
    float inv = rsqrtf(var + 1e-5f);
    float4 g4 = ((const float4*)gg)[tid];
    float4 b4 = ((const float4*)bb)[tid];
    float4 o;
    o.x = d0*inv*g4.x + b4.x;
    o.y = d1*inv*g4.y + b4.y;
    o.z = d2*inv*g4.z + b4.z;
    o.w = d3*inv*g4.w + b4.w;
    ((float4*)(Y + (size_t)row*Dd))[tid] = o;
}

// ---------------- SGEMM: C[M,N] (+)= act(A[M,K] @ B[K,N] + bias) ----------------
// 128x64x16 tile, 256 threads, 8x4 per thread. Requires N%64==0, K%16==0.
template<int ACT>  // 0 none, 1 gelu, 2 tanh
__global__ __launch_bounds__(256)
void sgemm_kernel(const float* __restrict__ A, const float* __restrict__ Bm,
                  float* __restrict__ C, int M, int N, int K,
                  const float* __restrict__ bias, int accum)
{
    __shared__ float As[16][128];
    __shared__ float Bs[16][64];
    const int tid = threadIdx.x;
    const int bm = blockIdx.y * 128;
    const int bn = blockIdx.x * 64;
    const int tm0 = (tid >> 4) * 8;
    const int tn0 = (tid & 15) * 4;
    const int arow = tid >> 2;
    const int acol = (tid & 3) << 2;
    const int brow = tid >> 4;
    const int bcol = (tid & 15) << 2;

    float acc[8][4];
#pragma unroll
    for (int i = 0; i < 8; i++)
#pragma unroll
        for (int j = 0; j < 4; j++) acc[i][j] = 0.f;

    for (int k0 = 0; k0 < K; k0 += 16) {
#pragma unroll
        for (int it = 0; it < 2; it++) {
            int r  = arow + it*64;
            int gr = bm + r;
            float4 v = make_float4(0.f, 0.f, 0.f, 0.f);
            if (gr < M) v = *(const float4*)(A + (size_t)gr*K + k0 + acol);
            As[acol+0][r] = v.x; As[acol+1][r] = v.y;
            As[acol+2][r] = v.z; As[acol+3][r] = v.w;
        }
        {
            float4 v = *(const float4*)(Bm + (size_t)(k0 + brow)*N + bn + bcol);
            *(float4*)&Bs[brow][bcol] = v;
        }
        __syncthreads();
#pragma unroll
        for (int k = 0; k < 16; k++) {
            float4 a0 = *(const float4*)&As[k][tm0];
            float4 a1 = *(const float4*)&As[k][tm0 + 4];
            float4 bv = *(const float4*)&Bs[k][tn0];
            float av[8] = {a0.x, a0.y, a0.z, a0.w, a1.x, a1.y, a1.z, a1.w};
            float bw[4] = {bv.x, bv.y, bv.z, bv.w};
#pragma unroll
            for (int i = 0; i < 8; i++)
#pragma unroll
                for (int j = 0; j < 4; j++)
                    acc[i][j] = fmaf(av[i], bw[j], acc[i][j]);
        }
        __syncthreads();
    }
#pragma unroll
    for (int i = 0; i < 8; i++) {
        int gr = bm + tm0 + i;
        if (gr >= M) break;
#pragma unroll
        for (int j = 0; j < 4; j++) {
            int gc = bn + tn0 + j;
            float v = acc[i][j];
            if (bias) v += bias[gc];
            if (ACT == 1) v = gelu_f(v);
            else if (ACT == 2) v = tanhf(v);
            size_t ci = (size_t)gr*N + gc;
            if (accum) C[ci] += v; else C[ci] = v;
        }
    }
}

// ---------------- feature attention: 32 queries x 32 keys x 64, per (b,t,head) ----------------
__global__ __launch_bounds__(256)
void fa_attn_kernel(const float* __restrict__ qkv, float* __restrict__ o)
{
    __shared__ float Qs[32][64], Ks[32][64], Vs[32][64], Ss[32][33];
    const int bt = blockIdx.x;           // b*16 + t
    const int h  = blockIdx.y;
    const int base = bt * 32;
    const int tid = threadIdx.x;
    for (int i = tid; i < 32*64; i += 256) {
        int f = i >> 6, d = i & 63;
        size_t r = (size_t)(base + f)*1536 + h*64 + d;
        Qs[f][d] = qkv[r];
        Ks[f][d] = qkv[r + 512];
        Vs[f][d] = qkv[r + 1024];
    }
    __syncthreads();
    for (int i = tid; i < 1024; i += 256) {
        int qi = i >> 5, ki = i & 31;
        float s = 0.f;
#pragma unroll
        for (int d = 0; d < 64; d++) s += Qs[qi][d]*Ks[ki][d];
        Ss[qi][ki] = s * 0.125f;
    }
    __syncthreads();
    const int w = tid >> 5, lane = tid & 31;
    for (int qi = w; qi < 32; qi += 8) {
        float v = Ss[qi][lane];
        float m = v;
#pragma unroll
        for (int oo = 16; oo > 0; oo >>= 1) m = fmaxf(m, __shfl_xor_sync(0xffffffffu, m, oo));
        float e  = expf(v - m);
        float su = e;
#pragma unroll
        for (int oo = 16; oo > 0; oo >>= 1) su += __shfl_xor_sync(0xffffffffu, su, oo);
        Ss[qi][lane] = e / su;
    }
    __syncthreads();
    for (int i = tid; i < 2048; i += 256) {
        int f = i >> 6, d = i & 63;
        float a = 0.f;
#pragma unroll
        for (int k = 0; k < 32; k++) a += Ss[f][k]*Vs[k][d];
        o[(size_t)(base + f)*512 + h*64 + d] = a;
    }
}

// ---------------- horse attention: 16 x 16 x 64, per (b,f,head), strided rows, key-masked ----------------
__global__ __launch_bounds__(128)
void ha_attn_kernel(const float* __restrict__ qkv, float* __restrict__ o,
                    const float* __restrict__ amask)
{
    __shared__ float Qs[16][64], Ks[16][64], Vs[16][64], Ss[16][17];
    const int bf = blockIdx.x;           // b*32 + f
    const int h  = blockIdx.y;
    const int b  = bf >> 5, f = bf & 31;
    const int tid = threadIdx.x;
    for (int i = tid; i < 16*64; i += 128) {
        int t = i >> 6, d = i & 63;
        size_t r = (size_t)((b*16 + t)*32 + f)*1536 + h*64 + d;
        Qs[t][d] = qkv[r];
        Ks[t][d] = qkv[r + 512];
        Vs[t][d] = qkv[r + 1024];
    }
    __syncthreads();
    for (int i = tid; i < 256; i += 128) {
        int qi = i >> 4, ki = i & 15;
        float s = 0.f;
#pragma unroll
        for (int d = 0; d < 64; d++) s += Qs[qi][d]*Ks[ki][d];
        s *= 0.125f;
        float mk = (ki < 15) ? amask[b*15 + ki] : 1.f;
        Ss[qi][ki] = (mk > 0.f) ? s : -1e9f;
    }
    __syncthreads();
    if (tid < 16) {
        float m = -1e30f;
#pragma unroll
        for (int k = 0; k < 16; k++) m = fmaxf(m, Ss[tid][k]);
        float su = 0.f;
#pragma unroll
        for (int k = 0; k < 16; k++) { float e = expf(Ss[tid][k] - m); Ss[tid][k] = e; su += e; }
        float inv = 1.f / su;
#pragma unroll
        for (int k = 0; k < 16; k++) Ss[tid][k] *= inv;
    }
    __syncthreads();
    for (int i = tid; i < 1024; i += 128) {
        int t = i >> 6, d = i & 63;
        float a = 0.f;
#pragma unroll
        for (int k = 0; k < 16; k++) a += Ss[t][k]*Vs[k][d];
        o[(size_t)((b*16 + t)*32 + f)*512 + h*64 + d] = a;
    }
}

// ---------------- pooling ----------------
__global__ __launch_bounds__(128)
void rowdot_kernel(const float* __restrict__ T, const float* __restrict__ v,
                   float* __restrict__ out)
{
    int row = blockIdx.x, tid = threadIdx.x;
    float4 a = ((const float4*)(T + (size_t)row*Dd))[tid];
    float4 w = ((const float4*)v)[tid];
    float s = a.x*w.x + a.y*w.y + a.z*w.z + a.w*w.w;
    s = warp_sum(s);
    __shared__ float red[4];
    if ((tid & 31) == 0) red[tid >> 5] = s;
    __syncthreads();
    if (tid == 0) out[row] = red[0]+red[1]+red[2]+red[3];
}

__global__ __launch_bounds__(256)
void pool_kernel(const float* __restrict__ s, const float* __restrict__ seq,
                 float* __restrict__ pooled)
{
    int bt = blockIdx.x;                 // b*16 + t  (t=15 -> race ctx)
    int tid = threadIdx.x;
    __shared__ float aw[32];
    if (tid < 32) {
        float v = s[bt*32 + tid];
        float m = v;
#pragma unroll
        for (int o = 16; o > 0; o >>= 1) m = fmaxf(m, __shfl_xor_sync(0xffffffffu, m, o));
        float e  = expf(v - m);
        float su = e;
#pragma unroll
        for (int o = 16; o > 0; o >>= 1) su += __shfl_xor_sync(0xffffffffu, su, o);
        aw[tid] = e / su;
    }
    __syncthreads();
    for (int d = tid; d < Dd; d += 256) {
        float acc = 0.f;
#pragma unroll
        for (int f = 0; f < 32; f++) acc += aw[f]*seq[((size_t)bt*32 + f)*Dd + d];
        pooled[(size_t)bt*Dd + d] = acc;
    }
}

__global__ __launch_bounds__(256)
void combine_kernel(const float* __restrict__ pooled, float* __restrict__ comb)
{
    int idx = blockIdx.x*256 + threadIdx.x;        // < 960*1024 (exact)
    int bh = idx >> 10;
    int c  = idx & 1023;
    int b = bh / 15, h = bh % 15;
    float v = (c < 512) ? pooled[(b*16 + h)*Dd + c]
                        : pooled[(b*16 + 15)*Dd + (c - 512)];
    comb[idx] = v;
}

__global__ __launch_bounds__(256)
void maskmul_kernel(float* __restrict__ feat, const float* __restrict__ amask)
{
    int idx = blockIdx.x*256 + threadIdx.x;        // < 960*512 (exact)
    feat[idx] *= amask[idx >> 9];
}

// ---------------- MCMC: one block per (b,h), analytic energy gradient ----------------
__global__ __launch_bounds__(512)
void mcmc_kernel(const float* __restrict__ U, const float* __restrict__ e_w1,
                 const float* __restrict__ e_w2, const float* __restrict__ amask,
                 const float* __restrict__ pred0, const int* __restrict__ nsteps,
                 float* __restrict__ out)
{
    const int bh = blockIdx.x;
    const int b  = bh / 15;
    const int j  = threadIdx.x;
    const float u  = U[(size_t)bh*Dd + j];
    const float wj = e_w1[512*512 + j];            // last row of e_w1 (the p channel)
    const float wc = wj * e_w2[j];
    const float mk = amask[bh];
    __shared__ float red[16];
    __shared__ float sp, shpr;
    if (j == 0) {
        float s = 0.f;
        for (int i = 0; i < 15; i++) s += amask[b*15 + i];
        shpr = s;
        sp = pred0[bh];
    }
    __syncthreads();
    const int n = *nsteps;
    for (int st = 0; st < n; st++) {
        float p = sp;
        float a = u + p*wj;
        float v = gelu_grad(a) * wc;
        v = warp_sum(v);
        if ((j & 31) == 0) red[j >> 5] = v;
        __syncthreads();
        if (j == 0) {
            float de = 0.f;
#pragma unroll
            for (int w = 0; w < 16; w++) de += red[w];
            float dent = -( logf(p + EPSc) + p/(p + EPSc)
                          - logf(1.f - p + EPSc) - (1.f - p)/(1.f - p + EPSc) );
            float g = (mk/(shpr*64.f)) * (de - 0.05f*dent);
            p = p - 0.1f*g*mk;
            p = (tanhf(p - 0.5f) + 1.f)*0.5f*(1.f - 2e-7f) + 1e-7f;
            p = fminf(fmaxf(p, EPSc), 1.f - EPSc);
            sp = p;
        }
        __syncthreads();
    }
    if (j == 0) out[bh] = sp;
}

// ---------------- host launch ----------------
static void launch_gemm(int act, const float* A, const float* Bm, float* C,
                        int M, int N, int K, const float* bias, int accum)
{
    dim3 grid(N/64, (M + 127)/128);
    if (act == 0)      sgemm_kernel<0><<<grid, 256>>>(A, Bm, C, M, N, K, bias, accum);
    else if (act == 1) sgemm_kernel<1><<<grid, 256>>>(A, Bm, C, M, N, K, bias, accum);
    else               sgemm_kernel<2><<<grid, 256>>>(A, Bm, C, M, N, K, bias, accum);
}

extern "C" void kernel_launch(void* const* d_in, const int* in_sizes, int n_in,
                              void* d_out, int out_size)
{
    const float* x_cont  = (const float*)d_in[0];
    const int*   x_cat   = (const int*)  d_in[1];
    const float* amask   = (const float*)d_in[2];
    const float* pred0   = (const float*)d_in[3];
    const float* emb_w   = (const float*)d_in[4];
    const float* emb_b   = (const float*)d_in[5];
    const float* cat_emb = (const float*)d_in[6];
    const float* cls     = (const float*)d_in[7];
    const float* fa_wqkv = (const float*)d_in[8];
    const float* fa_wo   = (const float*)d_in[9];
    const float* ha_wqkv = (const float*)d_in[10];
    const float* ha_wo   = (const float*)d_in[11];
    const float* ffn_w1  = (const float*)d_in[12];
    const float* ffn_b1  = (const float*)d_in[13];
    const float* ffn_w2  = (const float*)d_in[14];
    const float* ffn_b2  = (const float*)d_in[15];
    const float* ln1_g   = (const float*)d_in[16];
    const float* ln1_b   = (const float*)d_in[17];
    const float* ln2_g   = (const float*)d_in[18];
    const float* ln2_b   = (const float*)d_in[19];
    const float* ln3_g   = (const float*)d_in[20];
    const float* ln3_b   = (const float*)d_in[21];
    const float* pool_w  = (const float*)d_in[22];
    const float* pool_b  = (const float*)d_in[23];
    const float* pool_v  = (const float*)d_in[24];
    const float* proj_w  = (const float*)d_in[25];
    const float* proj_b  = (const float*)d_in[26];
    const float* e_w1    = (const float*)d_in[27];
    const float* e_b1    = (const float*)d_in[28];
    const float* e_w2    = (const float*)d_in[29];
    /* e_b2 = d_in[30] — constant shift, drops out of the gradient */
    const int*   nsteps  = (const int*)  d_in[31];
    float* out = (float*)d_out;

    float *seq, *lnb, *qkv, *ffn, *sbuf, *pool, *comb, *feat, *ubuf;
    cudaGetSymbolAddress((void**)&seq,  g_seq);
    cudaGetSymbolAddress((void**)&lnb,  g_ln);
    cudaGetSymbolAddress((void**)&qkv,  g_qkv);
    cudaGetSymbolAddress((void**)&ffn,  g_ffn);
    cudaGetSymbolAddress((void**)&sbuf, g_s);
    cudaGetSymbolAddress((void**)&pool, g_pool);
    cudaGetSymbolAddress((void**)&comb, g_comb);
    cudaGetSymbolAddress((void**)&feat, g_feat);
    cudaGetSymbolAddress((void**)&ubuf, g_u);

    // embedding -> seq (B,16,32,512)
    embed_kernel<<<(NTOK*Dd)/256, 256>>>(x_cont, x_cat, emb_w, emb_b, cat_emb, cls, seq);

    for (int l = 0; l < Ll; l++) {
        // feature attention (axis F), no mask
        ln_kernel<<<NTOK, 128>>>(seq, lnb, ln1_g + l*Dd, ln1_b + l*Dd);
        launch_gemm(0, lnb, fa_wqkv + (size_t)l*Dd*3*Dd, qkv, NTOK, 3*Dd, Dd, nullptr, 0);
        fa_attn_kernel<<<dim3(Bb*Tt, NHh), 256>>>(qkv, lnb);
        launch_gemm(0, lnb, fa_wo + (size_t)l*Dd*Dd, seq, NTOK, Dd, Dd, nullptr, 1);

        // horse attention (axis T), key-masked, strided rows (no transpose)
        ln_kernel<<<NTOK, 128>>>(seq, lnb, ln2_g + l*Dd, ln2_b + l*Dd);
        launch_gemm(0, lnb, ha_wqkv + (size_t)l*Dd*3*Dd, qkv, NTOK, 3*Dd, Dd, nullptr, 0);
        ha_attn_kernel<<<dim3(Bb*Ff, NHh), 128>>>(qkv, lnb, amask);
        launch_gemm(0, lnb, ha_wo + (size_t)l*Dd*Dd, seq, NTOK, Dd, Dd, nullptr, 1);

        // FFN with fused gelu + residual
        ln_kernel<<<NTOK, 128>>>(seq, lnb, ln3_g + l*Dd, ln3_b + l*Dd);
        launch_gemm(1, lnb, ffn_w1 + (size_t)l*Dd*DFFf, ffn, NTOK, DFFf, Dd, ffn_b1 + l*DFFf, 0);
        launch_gemm(0, ffn, ffn_w2 + (size_t)l*DFFf*Dd, seq, NTOK, Dd, DFFf, ffn_b2 + l*Dd, 1);
    }

    // attention pooling over features (horse tokens t<15 and race cls t=15 together)
    launch_gemm(2, seq, pool_w, qkv, NTOK, Dd, Dd, pool_b, 0);     // tanh(z@W+b) -> reuse qkv buf
    rowdot_kernel<<<NTOK, 128>>>(qkv, pool_v, sbuf);
    pool_kernel<<<Bb*Tt, 256>>>(sbuf, seq, pool);
    combine_kernel<<<(Bb*Hh*1024)/256, 256>>>(pool, comb);
    launch_gemm(0, comb, proj_w, feat, Bb*Hh, Dd, 2*Dd, proj_b, 0);
    maskmul_kernel<<<(Bb*Hh*Dd)/256, 256>>>(feat, amask);

    // energy precompute (p-independent part of the hidden pre-activation)
    launch_gemm(0, feat, e_w1, ubuf, Bb*Hh, Dd, Dd, e_b1, 0);      // uses rows 0..511 of e_w1

    // MCMC langevin-ish steps with analytic gradient
    mcmc_kernel<<<Bb*Hh, 512>>>(ubuf, e_w1, e_w2, amask, pred0, nsteps, out);
}

// round 2
// speedup vs baseline: 2.1106x; 2.1106x over previous
#include <cuda_runtime.h>
#include <math.h>

// ---------------- problem constants ----------------
#define Bb   64
#define Hh   15
#define Tt   16      // H + 1 (cls)
#define Ff   32      // F_CONT + F_CAT
#define Dd   512
#define NHh  8
#define HDd  64
#define Ll   4
#define DFFf 2048
#define NTOK (Bb*Tt*Ff)          // 32768 rows
#define EPSc 1e-7f

// ---------------- scratch (device globals; no allocation allowed) ----------------
__device__ float g_seq [NTOK*Dd];        // activations
__device__ float g_ln  [NTOK*Dd];        // LN out / attn out
__device__ float g_qkv [NTOK*3*Dd];      // qkv (also reused as pool-tanh buf)
__device__ float g_ffn [NTOK*DFFf];      // ffn hidden
__device__ float g_s   [NTOK];           // pool scores
__device__ float g_pool[Bb*Tt*Dd];       // pooled per (b,t)
__device__ float g_comb[Bb*Hh*2*Dd];     // concat(horse, race_ctx)
__device__ float g_feat[Bb*Hh*Dd];       // projected features
__device__ float g_u   [Bb*Hh*Dd];       // energy pre-activation (p-independent part)

// ---------------- helpers ----------------
__device__ __forceinline__ float warp_sum(float v){
#pragma unroll
    for (int o = 16; o > 0; o >>= 1) v += __shfl_xor_sync(0xffffffffu, v, o);
    return v;
}

__device__ __forceinline__ float gelu_f(float x){
    float x3 = x*x*x;
    float t  = tanhf(0.7978845608028654f*(x + 0.044715f*x3));
    return 0.5f*x*(1.f + t);
}
__device__ __forceinline__ float gelu_grad(float x){
    float x2 = x*x;
    float t  = tanhf(0.7978845608028654f*(x + 0.044715f*x2*x));
    float sech2 = 1.f - t*t;
    return 0.5f*(1.f + t) + 0.5f*x*sech2*0.7978845608028654f*(1.f + 3.f*0.044715f*x2);
}

__device__ __forceinline__ float to_tf32(float x){
    unsigned u;
    asm("cvt.rna.tf32.f32 %0, %1;" : "=r"(u) : "f"(x));
    return __uint_as_float(u);
}

__device__ __forceinline__ void mma_tf32(float* c, const unsigned* a, unsigned b0, unsigned b1){
    asm volatile("mma.sync.aligned.m16n8k8.row.col.f32.tf32.tf32.f32 "
        "{%0,%1,%2,%3}, {%4,%5,%6,%7}, {%8,%9}, {%0,%1,%2,%3};\n"
        : "+f"(c[0]), "+f"(c[1]), "+f"(c[2]), "+f"(c[3])
        : "r"(a[0]), "r"(a[1]), "r"(a[2]), "r"(a[3]), "r"(b0), "r"(b1));
}

// ---------------- embedding ----------------
__global__ __launch_bounds__(256)
void embed_kernel(const float* __restrict__ x_cont, const int* __restrict__ x_cat,
                  const float* __restrict__ emb_w, const float* __restrict__ emb_b,
                  const float* __restrict__ cat_emb, const float* __restrict__ cls,
                  float* __restrict__ seq)
{
    int idx = blockIdx.x*256 + threadIdx.x;          // < NTOK*Dd (exact grid)
    int d = idx & 511;
    int f = (idx >> 9)  & 31;
    int t = (idx >> 14) & 15;
    int b =  idx >> 18;
    float v;
    if (t == Tt-1) {
        v = cls[f*Dd + d];
    } else if (f < 24) {
        v = x_cont[(b*Hh + t)*24 + f]*emb_w[f*Dd + d] + emb_b[f*Dd + d];
    } else {
        int fc = f - 24;
        int c  = x_cat[(b*Hh + t)*8 + fc];
        v = cat_emb[((size_t)fc*50 + c)*Dd + d];
    }
    seq[idx] = v;
}

// ---------------- layernorm (one 128-thread block per row, D=512) ----------------
__global__ __launch_bounds__(128)
void ln_kernel(const float* __restrict__ X, float* __restrict__ Y,
               const float* __restrict__ gg, const float* __restrict__ bb)
{
    int row = blockIdx.x;
    int tid = threadIdx.x;
    const float4* xr = (const float4*)(X + (size_t)row*Dd);
    float4 v = xr[tid];
    __shared__ float red[4];
    float s = v.x + v.y + v.z + v.w;
    s = warp_sum(s);
    if ((tid & 31) == 0) red[tid >> 5] = s;
    __syncthreads();
    float mean = (red[0]+red[1]+red[2]+red[3]) * (1.f/Dd);
    float d0 = v.x-mean, d1 = v.y-mean, d2 = v.z-mean, d3 = v.w-mean;
    float q = d0*d0 + d1*d1 + d2*d2 + d3*d3;
    __syncthreads();
    q = warp_sum(q);
    if ((tid & 31) == 0) red[tid >> 5] = q;
    __syncthreads();
    float var = (red[0]+red[1]+red[2]+red[3]) * (1.f/Dd);
    float inv = rsqrtf(var + 1e-5f);
    float4 g4 = ((const float4*)gg)[tid];
    float4 b4 = ((const float4*)bb)[tid];
    float4 o;
    o.x = d0*inv*g4.x + b4.x;
    o.y = d1*inv*g4.y + b4.y;
    o.z = d2*inv*g4.z + b4.z;
    o.w = d3*inv*g4.w + b4.w;
    ((float4*)(Y + (size_t)row*Dd))[tid] = o;
}

// ---------------- TF32 tensor-core GEMM ----------------
// C[M,N] (+)= act(A[M,K] @ B[K,N] + bias). Block tile 128x128x16, 256 threads,
// 8 warps as 4(M) x 2(N); warp tile 32x64 = 2x8 m16n8k8 mma tiles.
// Requires N % 128 == 0, K % 16 == 0. A rows zero-padded past M.
template<int ACT>  // 0 none, 1 gelu, 2 tanh
__global__ __launch_bounds__(256)
void mmgemm_kernel(const float* __restrict__ A, const float* __restrict__ Bm,
                   float* __restrict__ C, int M, int N, int K,
                   const float* __restrict__ bias, int accum)
{
    __shared__ float As[2][16][132];   // [k][m], padded row = 132 (528B, 16B-mult)
    __shared__ float Bs[2][16][132];   // [k][n]
    const int tid  = threadIdx.x;
    const int lane = tid & 31;
    const int warp = tid >> 5;
    const int wm0  = (warp >> 1) * 32;
    const int wn0  = (warp & 1) * 64;
    const int g    = lane >> 2;
    const int tg   = lane & 3;
    const int bm   = blockIdx.y * 128;
    const int bn   = blockIdx.x * 128;

    // staging indices: A coalesced along K (float4), transposed store to [k][m]
    const int ar = tid >> 2;           // row 0..63 (+64 for it=1)
    const int ac = (tid & 3) * 4;      // k col 0,4,8,12

    float acc[2][8][4];
#pragma unroll
    for (int i = 0; i < 2; i++)
#pragma unroll
        for (int j = 0; j < 8; j++)
#pragma unroll
            for (int q = 0; q < 4; q++) acc[i][j][q] = 0.f;

    const int nk = K >> 4;

    // stage tile 0 into buffer 0
#pragma unroll
    for (int it = 0; it < 2; it++) {
        int row = ar + it*64;
        int grr = bm + row;
        float4 v = make_float4(0.f,0.f,0.f,0.f);
        if (grr < M) v = *(const float4*)(A + (size_t)grr*K + ac);
        As[0][ac+0][row] = to_tf32(v.x);
        As[0][ac+1][row] = to_tf32(v.y);
        As[0][ac+2][row] = to_tf32(v.z);
        As[0][ac+3][row] = to_tf32(v.w);
        int idx  = tid + it*256;
        int krow = idx >> 5;
        int c4   = (idx & 31) * 4;
        float4 w = *(const float4*)(Bm + (size_t)krow*N + bn + c4);
        float4 wt = make_float4(to_tf32(w.x), to_tf32(w.y), to_tf32(w.z), to_tf32(w.w));
        *(float4*)&Bs[0][krow][c4] = wt;
    }
    __syncthreads();

    for (int kt = 0; kt < nk; kt++) {
        const int cur = kt & 1, nxt = cur ^ 1;
        const bool more = (kt + 1 < nk);
        float4 pa[2], pb[2];
        if (more) {
            int k0 = (kt + 1) << 4;
#pragma unroll
            for (int it = 0; it < 2; it++) {
                int row = ar + it*64;
                int grr = bm + row;
                pa[it] = make_float4(0.f,0.f,0.f,0.f);
                if (grr < M) pa[it] = *(const float4*)(A + (size_t)grr*K + k0 + ac);
                int idx  = tid + it*256;
                int krow = idx >> 5;
                int c4   = (idx & 31) * 4;
                pb[it] = *(const float4*)(Bm + (size_t)(k0 + krow)*N + bn + c4);
            }
        }
        // compute on buffer cur: 2 k-steps of 8
#pragma unroll
        for (int kk = 0; kk < 2; kk++) {
            const int kb = kk * 8;
            unsigned af[2][4];
#pragma unroll
            for (int i = 0; i < 2; i++) {
                int m0 = wm0 + i*16;
                af[i][0] = __float_as_uint(As[cur][kb+tg  ][m0+g  ]);
                af[i][1] = __float_as_uint(As[cur][kb+tg  ][m0+g+8]);
                af[i][2] = __float_as_uint(As[cur][kb+tg+4][m0+g  ]);
                af[i][3] = __float_as_uint(As[cur][kb+tg+4][m0+g+8]);
            }
#pragma unroll
            for (int j = 0; j < 8; j++) {
                unsigned b0 = __float_as_uint(Bs[cur][kb+tg  ][wn0+j*8+g]);
                unsigned b1 = __float_as_uint(Bs[cur][kb+tg+4][wn0+j*8+g]);
                mma_tf32(acc[0][j], af[0], b0, b1);
                mma_tf32(acc[1][j], af[1], b0, b1);
            }
        }
        if (more) {
#pragma unroll
            for (int it = 0; it < 2; it++) {
                int row = ar + it*64;
                As[nxt][ac+0][row] = to_tf32(pa[it].x);
                As[nxt][ac+1][row] = to_tf32(pa[it].y);
                As[nxt][ac+2][row] = to_tf32(pa[it].z);
                As[nxt][ac+3][row] = to_tf32(pa[it].w);
                int idx  = tid + it*256;
                int krow = idx >> 5;
                int c4   = (idx & 31) * 4;
                float4 wt = make_float4(to_tf32(pb[it].x), to_tf32(pb[it].y),
                                        to_tf32(pb[it].z), to_tf32(pb[it].w));
                *(float4*)&Bs[nxt][krow][c4] = wt;
            }
        }
        __syncthreads();
    }

    // epilogue
#pragma unroll
    for (int i = 0; i < 2; i++) {
#pragma unroll
        for (int j = 0; j < 8; j++) {
            int col = bn + wn0 + j*8 + tg*2;
#pragma unroll
            for (int hh = 0; hh < 2; hh++) {
                int row = bm + wm0 + i*16 + g + hh*8;
                if (row < M) {
#pragma unroll
                    for (int q = 0; q < 2; q++) {
                        float v = acc[i][j][hh*2 + q];
                        int cc = col + q;
                        if (bias) v += bias[cc];
                        if (ACT == 1) v = gelu_f(v);
                        else if (ACT == 2) v = tanhf(v);
                        size_t ci = (size_t)row*N + cc;
                        if (accum) C[ci] += v; else C[ci] = v;
                    }
                }
            }
        }
    }
}

// ---------------- feature attention: 32 q x 32 k x 64, per (b,t,head) ----------------
__global__ __launch_bounds__(256)
void fa_attn_kernel(const float* __restrict__ qkv, float* __restrict__ o)
{
    __shared__ float Qs[32][65], Ks[32][65], Vs[32][65], Ss[32][33];
    const int bt = blockIdx.x;           // b*16 + t
    const int h  = blockIdx.y;
    const int base = bt * 32;
    const int tid = threadIdx.x;
    for (int i = tid; i < 32*64; i += 256) {
        int f = i >> 6, d = i & 63;
        size_t r = (size_t)(base + f)*1536 + h*64 + d;
        Qs[f][d] = qkv[r];
        Ks[f][d] = qkv[r + 512];
        Vs[f][d] = qkv[r + 1024];
    }
    __syncthreads();
    for (int i = tid; i < 1024; i += 256) {
        int qi = i >> 5, ki = i & 31;
        float s = 0.f;
#pragma unroll
        for (int d = 0; d < 64; d++) s += Qs[qi][d]*Ks[ki][d];
        Ss[qi][ki] = s * 0.125f;
    }
    __syncthreads();
    const int w = tid >> 5, lane = tid & 31;
    for (int qi = w; qi < 32; qi += 8) {
        float v = Ss[qi][lane];
        float m = v;
#pragma unroll
        for (int oo = 16; oo > 0; oo >>= 1) m = fmaxf(m, __shfl_xor_sync(0xffffffffu, m, oo));
        float e  = expf(v - m);
        float su = e;
#pragma unroll
        for (int oo = 16; oo > 0; oo >>= 1) su += __shfl_xor_sync(0xffffffffu, su, oo);
        Ss[qi][lane] = e / su;
    }
    __syncthreads();
    for (int i = tid; i < 2048; i += 256) {
        int f = i >> 6, d = i & 63;
        float a = 0.f;
#pragma unroll
        for (int k = 0; k < 32; k++) a += Ss[f][k]*Vs[k][d];
        o[(size_t)(base + f)*512 + h*64 + d] = a;
    }
}

// ---------------- horse attention: 16 x 16 x 64, per (b,f,head), key-masked ----------------
__global__ __launch_bounds__(128)
void ha_attn_kernel(const float* __restrict__ qkv, float* __restrict__ o,
                    const float* __restrict__ amask)
{
    __shared__ float Qs[16][65], Ks[16][65], Vs[16][65], Ss[16][17];
    const int bf = blockIdx.x;           // b*32 + f
    const int h  = blockIdx.y;
    const int b  = bf >> 5, f = bf & 31;
    const int tid = threadIdx.x;
    for (int i = tid; i < 16*64; i += 128) {
        int t = i >> 6, d = i & 63;
        size_t r = (size_t)((b*16 + t)*32 + f)*1536 + h*64 + d;
        Qs[t][d] = qkv[r];
        Ks[t][d] = qkv[r + 512];
        Vs[t][d] = qkv[r + 1024];
    }
    __syncthreads();
    for (int i = tid; i < 256; i += 128) {
        int qi = i >> 4, ki = i & 15;
        float s = 0.f;
#pragma unroll
        for (int d = 0; d < 64; d++) s += Qs[qi][d]*Ks[ki][d];
        s *= 0.125f;
        float mk = (ki < 15) ? amask[b*15 + ki] : 1.f;
        Ss[qi][ki] = (mk > 0.f) ? s : -1e9f;
    }
    __syncthreads();
    if (tid < 16) {
        float m = -1e30f;
#pragma unroll
        for (int k = 0; k < 16; k++) m = fmaxf(m, Ss[tid][k]);
        float su = 0.f;
#pragma unroll
        for (int k = 0; k < 16; k++) { float e = expf(Ss[tid][k] - m); Ss[tid][k] = e; su += e; }
        float inv = 1.f / su;
#pragma unroll
        for (int k = 0; k < 16; k++) Ss[tid][k] *= inv;
    }
    __syncthreads();
    for (int i = tid; i < 1024; i += 128) {
        int t = i >> 6, d = i & 63;
        float a = 0.f;
#pragma unroll
        for (int k = 0; k < 16; k++) a += Ss[t][k]*Vs[k][d];
        o[(size_t)((b*16 + t)*32 + f)*512 + h*64 + d] = a;
    }
}

// ---------------- pooling ----------------
__global__ __launch_bounds__(128)
void rowdot_kernel(const float* __restrict__ T, const float* __restrict__ v,
                   float* __restrict__ out)
{
    int row = blockIdx.x, tid = threadIdx.x;
    float4 a = ((const float4*)(T + (size_t)row*Dd))[tid];
    float4 w = ((const float4*)v)[tid];
    float s = a.x*w.x + a.y*w.y + a.z*w.z + a.w*w.w;
    s = warp_sum(s);
    __shared__ float red[4];
    if ((tid & 31) == 0) red[tid >> 5] = s;
    __syncthreads();
    if (tid == 0) out[row] = red[0]+red[1]+red[2]+red[3];
}

__global__ __launch_bounds__(256)
void pool_kernel(const float* __restrict__ s, const float* __restrict__ seq,
                 float* __restrict__ pooled)
{
    int bt = blockIdx.x;                 // b*16 + t  (t=15 -> race ctx)
    int tid = threadIdx.x;
    __shared__ float aw[32];
    if (tid < 32) {
        float v = s[bt*32 + tid];
        float m = v;
#pragma unroll
        for (int o = 16; o > 0; o >>= 1) m = fmaxf(m, __shfl_xor_sync(0xffffffffu, m, o));
        float e  = expf(v - m);
        float su = e;
#pragma unroll
        for (int o = 16; o > 0; o >>= 1) su += __shfl_xor_sync(0xffffffffu, su, o);
        aw[tid] = e / su;
    }
    __syncthreads();
    for (int d = tid; d < Dd; d += 256) {
        float acc = 0.f;
#pragma unroll
        for (int f = 0; f < 32; f++) acc += aw[f]*seq[((size_t)bt*32 + f)*Dd + d];
        pooled[(size_t)bt*Dd + d] = acc;
    }
}

__global__ __launch_bounds__(256)
void combine_kernel(const float* __restrict__ pooled, float* __restrict__ comb)
{
    int idx = blockIdx.x*256 + threadIdx.x;        // < 960*1024 (exact)
    int bh = idx >> 10;
    int c  = idx & 1023;
    int b = bh / 15, h = bh % 15;
    float v = (c < 512) ? pooled[(b*16 + h)*Dd + c]
                        : pooled[(b*16 + 15)*Dd + (c - 512)];
    comb[idx] = v;
}

__global__ __launch_bounds__(256)
void maskmul_kernel(float* __restrict__ feat, const float* __restrict__ amask)
{
    int idx = blockIdx.x*256 + threadIdx.x;        // < 960*512 (exact)
    feat[idx] *= amask[idx >> 9];
}

// ---------------- MCMC: one block per (b,h), analytic energy gradient ----------------
__global__ __launch_bounds__(512)
void mcmc_kernel(const float* __restrict__ U, const float* __restrict__ e_w1,
                 const float* __restrict__ e_w2, const float* __restrict__ amask,
                 const float* __restrict__ pred0, const int* __restrict__ nsteps,
                 float* __restrict__ out)
{
    const int bh = blockIdx.x;
    const int b  = bh / 15;
    const int j  = threadIdx.x;
    const float u  = U[(size_t)bh*Dd + j];
    const float wj = e_w1[512*512 + j];            // last row of e_w1 (the p channel)
    const float wc = wj * e_w2[j];
    const float mk = amask[bh];
    __shared__ float red[16];
    __shared__ float sp, shpr;
    if (j == 0) {
        float s = 0.f;
        for (int i = 0; i < 15; i++) s += amask[b*15 + i];
        shpr = s;
        sp = pred0[bh];
    }
    __syncthreads();
    const int n = *nsteps;
    for (int st = 0; st < n; st++) {
        float p = sp;
        float a = u + p*wj;
        float v = gelu_grad(a) * wc;
        v = warp_sum(v);
        if ((j & 31) == 0) red[j >> 5] = v;
        __syncthreads();
        if (j == 0) {
            float de = 0.f;
#pragma unroll
            for (int w = 0; w < 16; w++) de += red[w];
            float dent = -( logf(p + EPSc) + p/(p + EPSc)
                          - logf(1.f - p + EPSc) - (1.f - p)/(1.f - p + EPSc) );
            float g = (mk/(shpr*64.f)) * (de - 0.05f*dent);
            p = p - 0.1f*g*mk;
            p = (tanhf(p - 0.5f) + 1.f)*0.5f*(1.f - 2e-7f) + 1e-7f;
            p = fminf(fmaxf(p, EPSc), 1.f - EPSc);
            sp = p;
        }
        __syncthreads();
    }
    if (j == 0) out[bh] = sp;
}

// ---------------- host launch ----------------
static void launch_gemm(int act, const float* A, const float* Bm, float* C,
                        int M, int N, int K, const float* bias, int accum)
{
    dim3 grid(N/128, (M + 127)/128);
    if (act == 0)      mmgemm_kernel<0><<<grid, 256>>>(A, Bm, C, M, N, K, bias, accum);
    else if (act == 1) mmgemm_kernel<1><<<grid, 256>>>(A, Bm, C, M, N, K, bias, accum);
    else               mmgemm_kernel<2><<<grid, 256>>>(A, Bm, C, M, N, K, bias, accum);
}

extern "C" void kernel_launch(void* const* d_in, const int* in_sizes, int n_in,
                              void* d_out, int out_size)
{
    const float* x_cont  = (const float*)d_in[0];
    const int*   x_cat   = (const int*)  d_in[1];
    const float* amask   = (const float*)d_in[2];
    const float* pred0   = (const float*)d_in[3];
    const float* emb_w   = (const float*)d_in[4];
    const float* emb_b   = (const float*)d_in[5];
    const float* cat_emb = (const float*)d_in[6];
    const float* cls     = (const float*)d_in[7];
    const float* fa_wqkv = (const float*)d_in[8];
    const float* fa_wo   = (const float*)d_in[9];
    const float* ha_wqkv = (const float*)d_in[10];
    const float* ha_wo   = (const float*)d_in[11];
    const float* ffn_w1  = (const float*)d_in[12];
    const float* ffn_b1  = (const float*)d_in[13];
    const float* ffn_w2  = (const float*)d_in[14];
    const float* ffn_b2  = (const float*)d_in[15];
    const float* ln1_g   = (const float*)d_in[16];
    const float* ln1_b   = (const float*)d_in[17];
    const float* ln2_g   = (const float*)d_in[18];
    const float* ln2_b   = (const float*)d_in[19];
    const float* ln3_g   = (const float*)d_in[20];
    const float* ln3_b   = (const float*)d_in[21];
    const float* pool_w  = (const float*)d_in[22];
    const float* pool_b  = (const float*)d_in[23];
    const float* pool_v  = (const float*)d_in[24];
    const float* proj_w  = (const float*)d_in[25];
    const float* proj_b  = (const float*)d_in[26];
    const float* e_w1    = (const float*)d_in[27];
    const float* e_b1    = (const float*)d_in[28];
    const float* e_w2    = (const float*)d_in[29];
    /* e_b2 = d_in[30] — constant shift, drops out of the gradient */
    const int*   nsteps  = (const int*)  d_in[31];
    float* out = (float*)d_out;

    float *seq, *lnb, *qkv, *ffn, *sbuf, *pool, *comb, *feat, *ubuf;
    cudaGetSymbolAddress((void**)&seq,  g_seq);
    cudaGetSymbolAddress((void**)&lnb,  g_ln);
    cudaGetSymbolAddress((void**)&qkv,  g_qkv);
    cudaGetSymbolAddress((void**)&ffn,  g_ffn);
    cudaGetSymbolAddress((void**)&sbuf, g_s);
    cudaGetSymbolAddress((void**)&pool, g_pool);
    cudaGetSymbolAddress((void**)&comb, g_comb);
    cudaGetSymbolAddress((void**)&feat, g_feat);
    cudaGetSymbolAddress((void**)&ubuf, g_u);

    // embedding -> seq (B,16,32,512)
    embed_kernel<<<(NTOK*Dd)/256, 256>>>(x_cont, x_cat, emb_w, emb_b, cat_emb, cls, seq);

    for (int l = 0; l < Ll; l++) {
        // feature attention (axis F), no mask
        ln_kernel<<<NTOK, 128>>>(seq, lnb, ln1_g + l*Dd, ln1_b + l*Dd);
        launch_gemm(0, lnb, fa_wqkv + (size_t)l*Dd*3*Dd, qkv, NTOK, 3*Dd, Dd, nullptr, 0);
        fa_attn_kernel<<<dim3(Bb*Tt, NHh), 256>>>(qkv, lnb);
        launch_gemm(0, lnb, fa_wo + (size_t)l*Dd*Dd, seq, NTOK, Dd, Dd, nullptr, 1);

        // horse attention (axis T), key-masked, strided rows (no transpose)
        ln_kernel<<<NTOK, 128>>>(seq, lnb, ln2_g + l*Dd, ln2_b + l*Dd);
        launch_gemm(0, lnb, ha_wqkv + (size_t)l*Dd*3*Dd, qkv, NTOK, 3*Dd, Dd, nullptr, 0);
        ha_attn_kernel<<<dim3(Bb*Ff, NHh), 128>>>(qkv, lnb, amask);
        launch_gemm(0, lnb, ha_wo + (size_t)l*Dd*Dd, seq, NTOK, Dd, Dd, nullptr, 1);

        // FFN with fused gelu + residual
        ln_kernel<<<NTOK, 128>>>(seq, lnb, ln3_g + l*Dd, ln3_b + l*Dd);
        launch_gemm(1, lnb, ffn_w1 + (size_t)l*Dd*DFFf, ffn, NTOK, DFFf, Dd, ffn_b1 + l*DFFf, 0);
        launch_gemm(0, ffn, ffn_w2 + (size_t)l*DFFf*Dd, seq, NTOK, Dd, DFFf, ffn_b2 + l*Dd, 1);
    }

    // attention pooling over features (horse tokens t<15 and race cls t=15 together)
    launch_gemm(2, seq, pool_w, qkv, NTOK, Dd, Dd, pool_b, 0);     // tanh(z@W+b) -> reuse qkv buf
    rowdot_kernel<<<NTOK, 128>>>(qkv, pool_v, sbuf);
    pool_kernel<<<Bb*Tt, 256>>>(sbuf, seq, pool);
    combine_kernel<<<(Bb*Hh*1024)/256, 256>>>(pool, comb);
    launch_gemm(0, comb, proj_w, feat, Bb*Hh, Dd, 2*Dd, proj_b, 0);
    maskmul_kernel<<<(Bb*Hh*Dd)/256, 256>>>(feat, amask);

    // energy precompute (p-independent part of the hidden pre-activation)
    launch_gemm(0, feat, e_w1, ubuf, Bb*Hh, Dd, Dd, e_b1, 0);      // uses rows 0..511 of e_w1

    // MCMC langevin-ish steps with analytic gradient
    mcmc_kernel<<<Bb*Hh, 512>>>(ubuf, e_w1, e_w2, amask, pred0, nsteps, out);
}

// round 4
// speedup vs baseline: 4.2999x; 2.0373x over previous
#include <cuda_runtime.h>
#include <cuda_fp16.h>
#include <math.h>

// ---------------- problem constants ----------------
#define Bb   64
#define Hh   15
#define Tt   16      // H + 1 (cls)
#define Ff   32      // F_CONT + F_CAT
#define Dd   512
#define NHh  8
#define HDd  64
#define Ll   4
#define DFFf 2048
#define NTOK (Bb*Tt*Ff)          // 32768 rows
#define EPSc 1e-7f

// weight-pool offsets (halves)
#define OFF_FAQKV 0
#define SZ_FAQKV  (4*512*1536)
#define OFF_FAWO  (OFF_FAQKV + SZ_FAQKV)
#define SZ_FAWO   (4*512*512)
#define OFF_HAQKV (OFF_FAWO + SZ_FAWO)
#define SZ_HAQKV  SZ_FAQKV
#define OFF_HAWO  (OFF_HAQKV + SZ_HAQKV)
#define SZ_HAWO   SZ_FAWO
#define OFF_FFN1  (OFF_HAWO + SZ_HAWO)
#define SZ_FFN1   (4*512*2048)
#define OFF_FFN2  (OFF_FFN1 + SZ_FFN1)
#define SZ_FFN2   SZ_FFN1
#define OFF_POOLW (OFF_FFN2 + SZ_FFN2)
#define SZ_POOLW  (512*512)
#define OFF_PROJW (OFF_POOLW + SZ_POOLW)
#define SZ_PROJW  (1024*512)
#define OFF_EW1   (OFF_PROJW + SZ_PROJW)
#define SZ_EW1    (512*512)
#define WH_TOTAL  (OFF_EW1 + SZ_EW1)

// ---------------- scratch (device globals; no allocation allowed) ----------------
__device__ float  g_seq [NTOK*Dd];        // fp32 residual stream
__device__ __half g_lnh [NTOK*Dd];        // LN out / attn out / cvt(seq)  (half)
__device__ __half g_qkvh[NTOK*3*Dd];      // qkv / pool-tanh buf           (half)
__device__ __half g_ffnh[NTOK*DFFf];      // ffn hidden                    (half)
__device__ __half g_wh  [WH_TOTAL];       // half weight pool
__device__ float  g_s   [NTOK];           // pool scores
__device__ float  g_pool[Bb*Tt*Dd];       // pooled per (b,t)
__device__ __half g_combh[Bb*Hh*2*Dd];    // concat(horse, race_ctx) half
__device__ float  g_feat[Bb*Hh*Dd];       // projected features fp32
__device__ __half g_feath[Bb*Hh*Dd];      // masked features half
__device__ float  g_u   [Bb*Hh*Dd];       // energy pre-activation

// ---------------- helpers ----------------
__device__ __forceinline__ float warp_sum(float v){
#pragma unroll
    for (int o = 16; o > 0; o >>= 1) v += __shfl_xor_sync(0xffffffffu, v, o);
    return v;
}
__device__ __forceinline__ float gelu_f(float x){
    float x3 = x*x*x;
    float t  = tanhf(0.7978845608028654f*(x + 0.044715f*x3));
    return 0.5f*x*(1.f + t);
}
__device__ __forceinline__ float gelu_grad(float x){
    float x2 = x*x;
    float t  = tanhf(0.7978845608028654f*(x + 0.044715f*x2*x));
    float sech2 = 1.f - t*t;
    return 0.5f*(1.f + t) + 0.5f*x*sech2*0.7978845608028654f*(1.f + 3.f*0.044715f*x2);
}
__device__ __forceinline__ unsigned smem_u32(const void* p){
    return (unsigned)__cvta_generic_to_shared(p);
}
__device__ __forceinline__ unsigned pack_h2(float a, float b){
    unsigned lo = (unsigned)__half_as_ushort(__float2half_rn(a));
    unsigned hi = (unsigned)__half_as_ushort(__float2half_rn(b));
    return lo | (hi << 16);
}
__device__ __forceinline__ void ldsm_x4(unsigned& r0, unsigned& r1, unsigned& r2, unsigned& r3, unsigned a){
    asm volatile("ldmatrix.sync.aligned.m8n8.x4.shared.b16 {%0,%1,%2,%3},[%4];\n"
        : "=r"(r0), "=r"(r1), "=r"(r2), "=r"(r3) : "r"(a));
}
__device__ __forceinline__ void ldsm_x4t(unsigned& r0, unsigned& r1, unsigned& r2, unsigned& r3, unsigned a){
    asm volatile("ldmatrix.sync.aligned.m8n8.x4.trans.shared.b16 {%0,%1,%2,%3},[%4];\n"
        : "=r"(r0), "=r"(r1), "=r"(r2), "=r"(r3) : "r"(a));
}
__device__ __forceinline__ void mma_f16(float* c, const unsigned* a, unsigned b0, unsigned b1){
    asm volatile("mma.sync.aligned.m16n8k16.row.col.f32.f16.f16.f32 "
        "{%0,%1,%2,%3}, {%4,%5,%6,%7}, {%8,%9}, {%0,%1,%2,%3};\n"
        : "+f"(c[0]), "+f"(c[1]), "+f"(c[2]), "+f"(c[3])
        : "r"(a[0]), "r"(a[1]), "r"(a[2]), "r"(a[3]), "r"(b0), "r"(b1));
}

// ---------------- fp32 -> fp16 conversion (vectorized; n % 1024 == 0) ----------------
__global__ __launch_bounds__(256)
void f2h_kernel(const float* __restrict__ in, __half* __restrict__ out)
{
    int i = (blockIdx.x*256 + threadIdx.x)*4;
    float4 v = *(const float4*)(in + i);
    uint2 o;
    o.x = pack_h2(v.x, v.y);
    o.y = pack_h2(v.z, v.w);
    *(uint2*)(out + i) = o;
}

// ---------------- embedding ----------------
__global__ __launch_bounds__(256)
void embed_kernel(const float* __restrict__ x_cont, const int* __restrict__ x_cat,
                  const float* __restrict__ emb_w, const float* __restrict__ emb_b,
                  const float* __restrict__ cat_emb, const float* __restrict__ cls,
                  float* __restrict__ seq)
{
    int idx = blockIdx.x*256 + threadIdx.x;
    int d = idx & 511;
    int f = (idx >> 9)  & 31;
    int t = (idx >> 14) & 15;
    int b =  idx >> 18;
    float v;
    if (t == Tt-1) {
        v = cls[f*Dd + d];
    } else if (f < 24) {
        v = x_cont[(b*Hh + t)*24 + f]*emb_w[f*Dd + d] + emb_b[f*Dd + d];
    } else {
        int fc = f - 24;
        int c  = x_cat[(b*Hh + t)*8 + fc];
        v = cat_emb[((size_t)fc*50 + c)*Dd + d];
    }
    seq[idx] = v;
}

// ---------------- layernorm: fp32 in, fp16 out ----------------
__global__ __launch_bounds__(128)
void ln_kernel(const float* __restrict__ X, __half* __restrict__ Y,
               const float* __restrict__ gg, const float* __restrict__ bb)
{
    int row = blockIdx.x;
    int tid = threadIdx.x;
    float4 v = ((const float4*)(X + (size_t)row*Dd))[tid];
    __shared__ float red[4];
    float s = v.x + v.y + v.z + v.w;
    s = warp_sum(s);
    if ((tid & 31) == 0) red[tid >> 5] = s;
    __syncthreads();
    float mean = (red[0]+red[1]+red[2]+red[3]) * (1.f/Dd);
    float d0 = v.x-mean, d1 = v.y-mean, d2 = v.z-mean, d3 = v.w-mean;
    float q = d0*d0 + d1*d1 + d2*d2 + d3*d3;
    __syncthreads();
    q = warp_sum(q);
    if ((tid & 31) == 0) red[tid >> 5] = q;
    __syncthreads();
    float var = (red[0]+red[1]+red[2]+red[3]) * (1.f/Dd);
    float inv = rsqrtf(var + 1e-5f);
    float4 g4 = ((const float4*)gg)[tid];
    float4 b4 = ((const float4*)bb)[tid];
    uint2 o;
    o.x = pack_h2(d0*inv*g4.x + b4.x, d1*inv*g4.y + b4.y);
    o.y = pack_h2(d2*inv*g4.z + b4.z, d3*inv*g4.w + b4.w);
    *(uint2*)(Y + (size_t)row*Dd + tid*4) = o;
}

// ---------------- fp16 tensor-core GEMM ----------------
// C[M,N] (+)= act(A[M,K] @ B[K,N] + bias); A,B half; C float or half.
// Block 128x128x32, 256 threads, 8 warps (4m x 2n), warp 32x64, mma m16n8k16.
// Requires N % 128 == 0, K % 32 == 0.
#define SAh 40      // A smem row stride (halves): 32 + 8 pad
#define SBh 136     // B smem row stride (halves): 128 + 8 pad
template<int ACT, int CHALF>   // ACT: 0 none, 1 gelu, 2 tanh
__global__ __launch_bounds__(256)
void hgemm_kernel(const __half* __restrict__ A, const __half* __restrict__ Bm,
                  void* __restrict__ Cv, int M, int N, int K,
                  const float* __restrict__ bias, int accum)
{
    __shared__ __align__(16) __half As[2][128*SAh];
    __shared__ __align__(16) __half Bs[2][32*SBh];
    const int tid  = threadIdx.x;
    const int lane = tid & 31;
    const int warp = tid >> 5;
    const int wm0  = (warp >> 1) * 32;
    const int wn0  = (warp & 1) * 64;
    const int bm   = blockIdx.y * 128;
    const int bn   = blockIdx.x * 128;
    const int g    = lane >> 2;
    const int tg   = lane & 3;

    // staging coords
    const int ar  = tid >> 1;            // A row 0..127
    const int akb = (tid & 1) * 16;      // A k-offset (halves)
    const int brr = tid >> 3;            // B k-row 0..31
    const int bnn = (tid & 7) * 16;      // B n-offset

    // ldmatrix lane coords
    const int a_m = wm0 + (lane & 15);
    const int a_k = (lane >> 4) * 8;
    const int b_mi = lane >> 3;
    const int b_kr = (b_mi & 1) * 8 + (lane & 7);
    const int b_nc = (b_mi >> 1) * 8;

    float acc[2][8][4];
#pragma unroll
    for (int i = 0; i < 2; i++)
#pragma unroll
        for (int j = 0; j < 8; j++)
#pragma unroll
            for (int q = 0; q < 4; q++) acc[i][j][q] = 0.f;

    const int nk = K >> 5;
    uint4 va0, va1, vb0, vb1;

    // ---- stage tile 0 ----
    {
        int gr = bm + ar;
        if (gr < M) {
            const uint4* p = (const uint4*)(A + (size_t)gr*K + akb);
            va0 = p[0]; va1 = p[1];
        } else { va0 = make_uint4(0,0,0,0); va1 = va0; }
        const uint4* p = (const uint4*)(Bm + (size_t)brr*N + bn + bnn);
        vb0 = p[0]; vb1 = p[1];
        *(uint4*)&As[0][ar*SAh + akb]     = va0;
        *(uint4*)&As[0][ar*SAh + akb + 8] = va1;
        *(uint4*)&Bs[0][brr*SBh + bnn]     = vb0;
        *(uint4*)&Bs[0][brr*SBh + bnn + 8] = vb1;
    }
    __syncthreads();

    for (int kt = 0; kt < nk; kt++) {
        const int cur = kt & 1, nxt = cur ^ 1;
        const bool more = (kt + 1 < nk);
        if (more) {
            int k0 = (kt + 1) << 5;
            int gr = bm + ar;
            if (gr < M) {
                const uint4* p = (const uint4*)(A + (size_t)gr*K + k0 + akb);
                va0 = p[0]; va1 = p[1];
            } else { va0 = make_uint4(0,0,0,0); va1 = va0; }
            const uint4* p = (const uint4*)(Bm + (size_t)(k0 + brr)*N + bn + bnn);
            vb0 = p[0]; vb1 = p[1];
        }
        const unsigned uA = smem_u32(&As[cur][0]);
        const unsigned uB = smem_u32(&Bs[cur][0]);
#pragma unroll
        for (int kk = 0; kk < 2; kk++) {
            unsigned af[2][4], bf[4][4];
#pragma unroll
            for (int i = 0; i < 2; i++) {
                unsigned addr = uA + (unsigned)(((a_m + i*16)*SAh + kk*16 + a_k) * 2);
                ldsm_x4(af[i][0], af[i][1], af[i][2], af[i][3], addr);
            }
#pragma unroll
            for (int jp = 0; jp < 4; jp++) {
                unsigned addr = uB + (unsigned)(((kk*16 + b_kr)*SBh + wn0 + jp*16 + b_nc) * 2);
                ldsm_x4t(bf[jp][0], bf[jp][1], bf[jp][2], bf[jp][3], addr);
            }
#pragma unroll
            for (int i = 0; i < 2; i++)
#pragma unroll
                for (int j = 0; j < 8; j++)
                    mma_f16(acc[i][j], af[i], bf[j>>1][(j&1)*2], bf[j>>1][(j&1)*2+1]);
        }
        if (more) {
            *(uint4*)&As[nxt][ar*SAh + akb]     = va0;
            *(uint4*)&As[nxt][ar*SAh + akb + 8] = va1;
            *(uint4*)&Bs[nxt][brr*SBh + bnn]     = vb0;
            *(uint4*)&Bs[nxt][brr*SBh + bnn + 8] = vb1;
        }
        __syncthreads();
    }

    // ---- epilogue ----
    float* Cf = (float*)Cv;
    __half* Ch = (__half*)Cv;
#pragma unroll
    for (int i = 0; i < 2; i++) {
#pragma unroll
        for (int hh = 0; hh < 2; hh++) {
            int row = bm + wm0 + i*16 + g + hh*8;
            if (row >= M) continue;
#pragma unroll
            for (int j = 0; j < 8; j++) {
                int col = bn + wn0 + j*8 + tg*2;
                float v0 = acc[i][j][hh*2 + 0];
                float v1 = acc[i][j][hh*2 + 1];
                if (bias) { v0 += bias[col]; v1 += bias[col+1]; }
                if (ACT == 1) { v0 = gelu_f(v0); v1 = gelu_f(v1); }
                else if (ACT == 2) { v0 = tanhf(v0); v1 = tanhf(v1); }
                if (CHALF) {
                    *(unsigned*)(Ch + (size_t)row*N + col) = pack_h2(v0, v1);
                } else {
                    size_t ci = (size_t)row*N + col;
                    if (accum) { Cf[ci] += v0; Cf[ci+1] += v1; }
                    else       { Cf[ci]  = v0; Cf[ci+1]  = v1; }
                }
            }
        }
    }
}

// ---------------- feature attention: 32 q x 32 k x 64 per (b,t,head); half io ----------------
__global__ __launch_bounds__(256)
void fa_attn_kernel(const __half* __restrict__ qkv, __half* __restrict__ o)
{
    __shared__ float Qs[32][68], Ks[32][68], Vs[32][68], Ss[32][36];
    const int bt = blockIdx.x;           // b*16 + t
    const int h  = blockIdx.y;
    const int base = bt * 32;
    const int tid = threadIdx.x;
    for (int i = tid; i < 32*32; i += 256) {
        int f = i >> 5, d2 = i & 31;
        size_t r = (size_t)(base + f)*1536 + h*64 + d2*2;
        float2 q = __half22float2(*(const __half2*)(qkv + r));
        float2 k = __half22float2(*(const __half2*)(qkv + r + 512));
        float2 v = __half22float2(*(const __half2*)(qkv + r + 1024));
        Qs[f][d2*2] = q.x; Qs[f][d2*2+1] = q.y;
        Ks[f][d2*2] = k.x; Ks[f][d2*2+1] = k.y;
        Vs[f][d2*2] = v.x; Vs[f][d2*2+1] = v.y;
    }
    __syncthreads();
    for (int i = tid; i < 1024; i += 256) {
        int qi = i >> 5, ki = i & 31;
        const float4* qp = (const float4*)Qs[qi];
        const float4* kp = (const float4*)Ks[ki];
        float s = 0.f;
#pragma unroll
        for (int d4 = 0; d4 < 16; d4++) {
            float4 a = qp[d4], b = kp[d4];
            s += a.x*b.x + a.y*b.y + a.z*b.z + a.w*b.w;
        }
        Ss[qi][ki] = s * 0.125f;
    }
    __syncthreads();
    const int w = tid >> 5, lane = tid & 31;
    for (int qi = w; qi < 32; qi += 8) {
        float v = Ss[qi][lane];
        float m = v;
#pragma unroll
        for (int oo = 16; oo > 0; oo >>= 1) m = fmaxf(m, __shfl_xor_sync(0xffffffffu, m, oo));
        float e  = expf(v - m);
        float su = e;
#pragma unroll
        for (int oo = 16; oo > 0; oo >>= 1) su += __shfl_xor_sync(0xffffffffu, su, oo);
        Ss[qi][lane] = e / su;
    }
    __syncthreads();
    for (int i = tid; i < 2048; i += 256) {
        int f = i >> 6, d = i & 63;
        const float4* sp = (const float4*)Ss[f];
        float a = 0.f;
#pragma unroll
        for (int k4 = 0; k4 < 8; k4++) {
            float4 sv = sp[k4];
            a += sv.x*Vs[k4*4+0][d] + sv.y*Vs[k4*4+1][d]
               + sv.z*Vs[k4*4+2][d] + sv.w*Vs[k4*4+3][d];
        }
        o[(size_t)(base + f)*512 + h*64 + d] = __float2half(a);
    }
}

// ---------------- horse attention: 16 x 16 x 64 per (b,f,head), key-masked; half io ----------------
__global__ __launch_bounds__(128)
void ha_attn_kernel(const __half* __restrict__ qkv, __half* __restrict__ o,
                    const float* __restrict__ amask)
{
    __shared__ float Qs[16][68], Ks[16][68], Vs[16][68], Ss[16][20];
    const int bf = blockIdx.x;           // b*32 + f
    const int h  = blockIdx.y;
    const int b  = bf >> 5, f = bf & 31;
    const int tid = threadIdx.x;
    for (int i = tid; i < 16*32; i += 128) {
        int t = i >> 5, d2 = i & 31;
        size_t r = (size_t)((b*16 + t)*32 + f)*1536 + h*64 + d2*2;
        float2 q = __half22float2(*(const __half2*)(qkv + r));
        float2 k = __half22float2(*(const __half2*)(qkv + r + 512));
        float2 v = __half22float2(*(const __half2*)(qkv + r + 1024));
        Qs[t][d2*2] = q.x; Qs[t][d2*2+1] = q.y;
        Ks[t][d2*2] = k.x; Ks[t][d2*2+1] = k.y;
        Vs[t][d2*2] = v.x; Vs[t][d2*2+1] = v.y;
    }
    __syncthreads();
    for (int i = tid; i < 256; i += 128) {
        int qi = i >> 4, ki = i & 15;
        const float4* qp = (const float4*)Qs[qi];
        const float4* kp = (const float4*)Ks[ki];
        float s = 0.f;
#pragma unroll
        for (int d4 = 0; d4 < 16; d4++) {
            float4 a = qp[d4], bb = kp[d4];
            s += a.x*bb.x + a.y*bb.y + a.z*bb.z + a.w*bb.w;
        }
        s *= 0.125f;
        float mk = (ki < 15) ? amask[b*15 + ki] : 1.f;
        Ss[qi][ki] = (mk > 0.f) ? s : -1e9f;
    }
    __syncthreads();
    if (tid < 16) {
        float m = -1e30f;
#pragma unroll
        for (int k = 0; k < 16; k++) m = fmaxf(m, Ss[tid][k]);
        float su = 0.f;
#pragma unroll
        for (int k = 0; k < 16; k++) { float e = expf(Ss[tid][k] - m); Ss[tid][k] = e; su += e; }
        float inv = 1.f / su;
#pragma unroll
        for (int k = 0; k < 16; k++) Ss[tid][k] *= inv;
    }
    __syncthreads();
    for (int i = tid; i < 1024; i += 128) {
        int t = i >> 6, d = i & 63;
        const float4* sp = (const float4*)Ss[t];
        float a = 0.f;
#pragma unroll
        for (int k4 = 0; k4 < 4; k4++) {
            float4 sv = sp[k4];
            a += sv.x*Vs[k4*4+0][d] + sv.y*Vs[k4*4+1][d]
               + sv.z*Vs[k4*4+2][d] + sv.w*Vs[k4*4+3][d];
        }
        o[(size_t)((b*16 + t)*32 + f)*512 + h*64 + d] = __float2half(a);
    }
}

// ---------------- pooling ----------------
__global__ __launch_bounds__(128)
void rowdot_kernel(const __half* __restrict__ T, const float* __restrict__ v,
                   float* __restrict__ out)
{
    int row = blockIdx.x, tid = threadIdx.x;
    const __half2* tr = (const __half2*)(T + (size_t)row*Dd);
    float2 a0 = __half22float2(tr[tid*2]);
    float2 a1 = __half22float2(tr[tid*2+1]);
    float4 w = ((const float4*)v)[tid];
    float s = a0.x*w.x + a0.y*w.y + a1.x*w.z + a1.y*w.w;
    s = warp_sum(s);
    __shared__ float red[4];
    if ((tid & 31) == 0) red[tid >> 5] = s;
    __syncthreads();
    if (tid == 0) out[row] = red[0]+red[1]+red[2]+red[3];
}

__global__ __launch_bounds__(256)
void pool_kernel(const float* __restrict__ s, const float* __restrict__ seq,
                 float* __restrict__ pooled)
{
    int bt = blockIdx.x;
    int tid = threadIdx.x;
    __shared__ float aw[32];
    if (tid < 32) {
        float v = s[bt*32 + tid];
        float m = v;
#pragma unroll
        for (int o = 16; o > 0; o >>= 1) m = fmaxf(m, __shfl_xor_sync(0xffffffffu, m, o));
        float e  = expf(v - m);
        float su = e;
#pragma unroll
        for (int o = 16; o > 0; o >>= 1) su += __shfl_xor_sync(0xffffffffu, su, o);
        aw[tid] = e / su;
    }
    __syncthreads();
    for (int d = tid; d < Dd; d += 256) {
        float acc = 0.f;
#pragma unroll
        for (int f = 0; f < 32; f++) acc += aw[f]*seq[((size_t)bt*32 + f)*Dd + d];
        pooled[(size_t)bt*Dd + d] = acc;
    }
}

__global__ __launch_bounds__(256)
void combine_kernel(const float* __restrict__ pooled, __half* __restrict__ comb)
{
    int idx = blockIdx.x*256 + threadIdx.x;        // < 960*1024
    int bh = idx >> 10;
    int c  = idx & 1023;
    int b = bh / 15, h = bh % 15;
    float v = (c < 512) ? pooled[(b*16 + h)*Dd + c]
                        : pooled[(b*16 + 15)*Dd + (c - 512)];
    comb[idx] = __float2half(v);
}

__global__ __launch_bounds__(256)
void maskmul_kernel(const float* __restrict__ feat, const float* __restrict__ amask,
                    __half* __restrict__ feath)
{
    int idx = blockIdx.x*256 + threadIdx.x;        // < 960*512
    feath[idx] = __float2half(feat[idx] * amask[idx >> 9]);
}

// ---------------- MCMC: one block per (b,h), analytic energy gradient ----------------
__global__ __launch_bounds__(512)
void mcmc_kernel(const float* __restrict__ U, const float* __restrict__ e_w1,
                 const float* __restrict__ e_w2, const float* __restrict__ amask,
                 const float* __restrict__ pred0, const int* __restrict__ nsteps,
                 float* __restrict__ out)
{
    const int bh = blockIdx.x;
    const int b  = bh / 15;
    const int j  = threadIdx.x;
    const float u  = U[(size_t)bh*Dd + j];
    const float wj = e_w1[512*512 + j];
    const float wc = wj * e_w2[j];
    const float mk = amask[bh];
    __shared__ float red[16];
    __shared__ float sp, shpr;
    if (j == 0) {
        float s = 0.f;
        for (int i = 0; i < 15; i++) s += amask[b*15 + i];
        shpr = s;
        sp = pred0[bh];
    }
    __syncthreads();
    const int n = *nsteps;
    for (int st = 0; st < n; st++) {
        float p = sp;
        float a = u + p*wj;
        float v = gelu_grad(a) * wc;
        v = warp_sum(v);
        if ((j & 31) == 0) red[j >> 5] = v;
        __syncthreads();
        if (j == 0) {
            float de = 0.f;
#pragma unroll
            for (int w = 0; w < 16; w++) de += red[w];
            float dent = -( logf(p + EPSc) + p/(p + EPSc)
                          - logf(1.f - p + EPSc) - (1.f - p)/(1.f - p + EPSc) );
            float g = (mk/(shpr*64.f)) * (de - 0.05f*dent);
            p = p - 0.1f*g*mk;
            p = (tanhf(p - 0.5f) + 1.f)*0.5f*(1.f - 2e-7f) + 1e-7f;
            p = fminf(fmaxf(p, EPSc), 1.f - EPSc);
            sp = p;
        }
        __syncthreads();
    }
    if (j == 0) out[bh] = sp;
}

// ---------------- host launch ----------------
static void launch_hgemm(int act, int chalf, const __half* A, const __half* Bm, void* C,
                         int M, int N, int K, const float* bias, int accum)
{
    dim3 grid(N/128, (M + 127)/128);
    if (chalf) {
        if (act == 0)      hgemm_kernel<0,1><<<grid, 256>>>(A, Bm, C, M, N, K, bias, accum);
        else if (act == 1) hgemm_kernel<1,1><<<grid, 256>>>(A, Bm, C, M, N, K, bias, accum);
        else               hgemm_kernel<2,1><<<grid, 256>>>(A, Bm, C, M, N, K, bias, accum);
    } else {
        if (act == 0)      hgemm_kernel<0,0><<<grid, 256>>>(A, Bm, C, M, N, K, bias, accum);
        else if (act == 1) hgemm_kernel<1,0><<<grid, 256>>>(A, Bm, C, M, N, K, bias, accum);
        else               hgemm_kernel<2,0><<<grid, 256>>>(A, Bm, C, M, N, K, bias, accum);
    }
}
static void launch_f2h(const float* in, __half* out, int n)
{
    f2h_kernel<<<n/1024, 256>>>(in, out);
}

extern "C" void kernel_launch(void* const* d_in, const int* in_sizes, int n_in,
                              void* d_out, int out_size)
{
    const float* x_cont  = (const float*)d_in[0];
    const int*   x_cat   = (const int*)  d_in[1];
    const float* amask   = (const float*)d_in[2];
    const float* pred0   = (const float*)d_in[3];
    const float* emb_w   = (const float*)d_in[4];
    const float* emb_b   = (const float*)d_in[5];
    const float* cat_emb = (const float*)d_in[6];
    const float* cls     = (const float*)d_in[7];
    const float* fa_wqkv = (const float*)d_in[8];
    const float* fa_wo   = (const float*)d_in[9];
    const float* ha_wqkv = (const float*)d_in[10];
    const float* ha_wo   = (const float*)d_in[11];
    const float* ffn_w1  = (const float*)d_in[12];
    const float* ffn_b1  = (const float*)d_in[13];
    const float* ffn_w2  = (const float*)d_in[14];
    const float* ffn_b2  = (const float*)d_in[15];
    const float* ln1_g   = (const float*)d_in[16];
    const float* ln1_b   = (const float*)d_in[17];
    const float* ln2_g   = (const float*)d_in[18];
    const float* ln2_b   = (const float*)d_in[19];
    const float* ln3_g   = (const float*)d_in[20];
    const float* ln3_b   = (const float*)d_in[21];
    const float* pool_w  = (const float*)d_in[22];
    const float* pool_b  = (const float*)d_in[23];
    const float* pool_v  = (const float*)d_in[24];
    const float* proj_w  = (const float*)d_in[25];
    const float* proj_b  = (const float*)d_in[26];
    const float* e_w1    = (const float*)d_in[27];
    const float* e_b1    = (const float*)d_in[28];
    const float* e_w2    = (const float*)d_in[29];
    const int*   nsteps  = (const int*)  d_in[31];
    float* out = (float*)d_out;

    float *seq, *sbuf, *pool, *feat, *ubuf;
    __half *lnh, *qkvh, *ffnh, *wh, *combh, *feath;
    cudaGetSymbolAddress((void**)&seq,  g_seq);
    cudaGetSymbolAddress((void**)&lnh,  g_lnh);
    cudaGetSymbolAddress((void**)&qkvh, g_qkvh);
    cudaGetSymbolAddress((void**)&ffnh, g_ffnh);
    cudaGetSymbolAddress((void**)&wh,   g_wh);
    cudaGetSymbolAddress((void**)&sbuf, g_s);
    cudaGetSymbolAddress((void**)&pool, g_pool);
    cudaGetSymbolAddress((void**)&combh,g_combh);
    cudaGetSymbolAddress((void**)&feat, g_feat);
    cudaGetSymbolAddress((void**)&feath,g_feath);
    cudaGetSymbolAddress((void**)&ubuf, g_u);

    // weight pre-conversion to fp16
    launch_f2h(fa_wqkv, wh + OFF_FAQKV, SZ_FAQKV);
    launch_f2h(fa_wo,   wh + OFF_FAWO,  SZ_FAWO);
    launch_f2h(ha_wqkv, wh + OFF_HAQKV, SZ_HAQKV);
    launch_f2h(ha_wo,   wh + OFF_HAWO,  SZ_HAWO);
    launch_f2h(ffn_w1,  wh + OFF_FFN1,  SZ_FFN1);
    launch_f2h(ffn_w2,  wh + OFF_FFN2,  SZ_FFN2);
    launch_f2h(pool_w,  wh + OFF_POOLW, SZ_POOLW);
    launch_f2h(proj_w,  wh + OFF_PROJW, SZ_PROJW);
    launch_f2h(e_w1,    wh + OFF_EW1,   SZ_EW1);   // rows 0..511 only

    // embedding -> seq (B,16,32,512) fp32
    embed_kernel<<<(NTOK*Dd)/256, 256>>>(x_cont, x_cat, emb_w, emb_b, cat_emb, cls, seq);

    for (int l = 0; l < Ll; l++) {
        // feature attention (axis F)
        ln_kernel<<<NTOK, 128>>>(seq, lnh, ln1_g + l*Dd, ln1_b + l*Dd);
        launch_hgemm(0, 1, lnh, wh + OFF_FAQKV + (size_t)l*Dd*3*Dd, qkvh, NTOK, 3*Dd, Dd, nullptr, 0);
        fa_attn_kernel<<<dim3(Bb*Tt, NHh), 256>>>(qkvh, lnh);
        launch_hgemm(0, 0, lnh, wh + OFF_FAWO + (size_t)l*Dd*Dd, seq, NTOK, Dd, Dd, nullptr, 1);

        // horse attention (axis T), key-masked, strided rows (no transpose)
        ln_kernel<<<NTOK, 128>>>(seq, lnh, ln2_g + l*Dd, ln2_b + l*Dd);
        launch_hgemm(0, 1, lnh, wh + OFF_HAQKV + (size_t)l*Dd*3*Dd, qkvh, NTOK, 3*Dd, Dd, nullptr, 0);
        ha_attn_kernel<<<dim3(Bb*Ff, NHh), 128>>>(qkvh, lnh, amask);
        launch_hgemm(0, 0, lnh, wh + OFF_HAWO + (size_t)l*Dd*Dd, seq, NTOK, Dd, Dd, nullptr, 1);

        // FFN with fused gelu + residual
        ln_kernel<<<NTOK, 128>>>(seq, lnh, ln3_g + l*Dd, ln3_b + l*Dd);
        launch_hgemm(1, 1, lnh, wh + OFF_FFN1 + (size_t)l*Dd*DFFf, ffnh, NTOK, DFFf, Dd, ffn_b1 + l*DFFf, 0);
        launch_hgemm(0, 0, ffnh, wh + OFF_FFN2 + (size_t)l*DFFf*Dd, seq, NTOK, Dd, DFFf, ffn_b2 + l*Dd, 1);
    }

    // attention pooling
    launch_f2h(seq, lnh, NTOK*Dd);                                     // seq -> half
    launch_hgemm(2, 1, lnh, wh + OFF_POOLW, qkvh, NTOK, Dd, Dd, pool_b, 0);   // tanh buf (half)
    rowdot_kernel<<<NTOK, 128>>>(qkvh, pool_v, sbuf);
    pool_kernel<<<Bb*Tt, 256>>>(sbuf, seq, pool);
    combine_kernel<<<(Bb*Hh*1024)/256, 256>>>(pool, combh);
    launch_hgemm(0, 0, combh, wh + OFF_PROJW, feat, Bb*Hh, Dd, 2*Dd, proj_b, 0);
    maskmul_kernel<<<(Bb*Hh*Dd)/256, 256>>>(feat, amask, feath);

    // energy precompute (p-independent part)
    launch_hgemm(0, 0, feath, wh + OFF_EW1, ubuf, Bb*Hh, Dd, Dd, e_b1, 0);

    // MCMC
    mcmc_kernel<<<Bb*Hh, 512>>>(ubuf, e_w1, e_w2, amask, pred0, nsteps, out);
}